// round 6
// baseline (speedup 1.0000x reference)
#include <cuda_runtime.h>
#include <stdint.h>

#define IN_W 256
#define IN_HW 65536
#define OUT_W 254

#define R_OUT 4            // output rows per CTA
#define ROWS_IN 6          // R_OUT + 2
#define POS 130            // 128 + 2 halo input positions
#define ROW_W 2080         // POS * 16 words per input row
#define A_WORDS (ROWS_IN * ROW_W)        // 12480
#define BF_WORDS 2304                    // 3 ky * 6 ks * 2 h * 32 lanes * 2 regs
#define SMEM_BYTES ((A_WORDS + BF_WORDS + 16) * 4)   // 59,200 B -> 3 CTAs/SM

// word-index swizzle: XOR bit5 into bit3.  Proven conflict-free for:
//  - A LDS.64 fragment loads (half-warp blocks {b,b+2,b+4,b+6} -> distinct octets)
//  - transpose STS.128 (per-phase blocks {b..b+3} -> distinct octets)
__device__ __forceinline__ uint32_t swzw(uint32_t w) {
    return w ^ ((w & 32u) >> 2);
}
__device__ __forceinline__ uint32_t tf32r(float f) {
    uint32_t r; asm("cvt.rna.tf32.f32 %0, %1;" : "=r"(r) : "f"(f)); return r;
}
__device__ __forceinline__ void mma_tf32(float c[4], uint32_t a0, uint32_t a1,
                                         uint32_t a2, uint32_t a3,
                                         uint32_t b0, uint32_t b1) {
    asm("mma.sync.aligned.m16n8k8.row.col.f32.tf32.tf32.f32 "
        "{%0,%1,%2,%3}, {%4,%5,%6,%7}, {%8,%9}, {%0,%1,%2,%3};"
        : "+f"(c[0]), "+f"(c[1]), "+f"(c[2]), "+f"(c[3])
        : "r"(a0), "r"(a1), "r"(a2), "r"(a3), "r"(b0), "r"(b1));
}
__device__ __forceinline__ float mish_f(float v) {
    if (v > 30.0f) return v;
    float e  = __expf(v);
    float t  = 1.0f + e;
    float t2 = t * t;
    return v * __fdividef(t2 - 1.0f, t2 + 1.0f);
}

__global__ __launch_bounds__(256, 3)
void conv_tc_kernel(const float* __restrict__ x,
                    const float* __restrict__ w,
                    const float* __restrict__ bias,
                    float* __restrict__ y)
{
    extern __shared__ uint32_t sm[];
    uint32_t* Asm = sm;                     // [row][pos][ci-permuted], swizzled tf32
    uint32_t* Bf  = sm + A_WORDS;           // lane-ordered B fragments (unswizzled)
    float*    bsm = (float*)(sm + A_WORDS + BF_WORDS);

    const int tid  = threadIdx.x;
    const int wid  = tid >> 5;
    const int lane = tid & 31;
    const int lm   = lane >> 2;
    const int lk   = lane & 3;
    const int X0   = blockIdx.x * 128;
    const int Y0   = blockIdx.y * R_OUT;
    const int n    = blockIdx.z;

    if (tid < 16) bsm[tid] = bias[tid];

    // ---- B fragments: Bf[(ky*6+ks)*128 + h*64 + lane*2 + reg]
    for (int i = tid; i < BF_WORDS; i += 256) {
        int reg = i & 1;
        int ln  = (i >> 1) & 31;
        int h   = (i >> 6) & 1;
        int t   = i >> 7;              // ky*6+ks
        int ks  = t % 6, ky = t / 6;
        int k   = ks * 8 + (ln & 3) + reg * 4;
        int co  = h * 8 + (ln >> 2);
        int kx  = k >> 4, ci = k & 15;
        Bf[i] = tf32r(w[(co * 16 + ci) * 9 + ky * 3 + kx]);
    }

    // ---- input transpose: NCHW -> smem [row][pos][ci-permuted], tf32, swizzled.
    // permuted slot order per position: [0,4,1,5,2,6,3,7, 8,12,9,13,10,14,11,15]
    // thread item = (row, pos, quarter): one STS.128 of 4 permuted slots.
    const float* xn = x + (size_t)n * 16 * IN_HW;
    for (int i = tid; i < ROWS_IN * POS * 4; i += 256) {
        int qt  = i & 3;
        int pos = (i >> 2) % POS;
        int row = (i >> 2) / POS;
        int gy = Y0 + row; if (gy > 255) gy = 255;   // clamped rows feed guarded outputs only
        int gx = X0 + pos; if (gx > 255) gx = 255;
        const float* src = xn + gy * IN_W + gx;
        int cb = (qt >> 1) * 8 + (qt & 1) * 2;
        uint4 v;
        v.x = tf32r(src[(size_t)(cb    ) * IN_HW]);
        v.y = tf32r(src[(size_t)(cb + 4) * IN_HW]);
        v.z = tf32r(src[(size_t)(cb + 1) * IN_HW]);
        v.w = tf32r(src[(size_t)(cb + 5) * IN_HW]);
        *(uint4*)(Asm + swzw((uint32_t)(row * ROW_W + pos * 16 + qt * 4))) = v;
    }
    __syncthreads();

    // ---- mainloop: warp = (row wid>>1, x-half wid&1), 4 tiles of 16 x-positions
    const int r  = wid >> 1;
    const int yo = Y0 + r;
    const int xh = (wid & 1) * 64;

    #pragma unroll 1
    for (int t = 0; t < 4; t++) {
        const int posbase = xh + t * 16;
        float c0[4] = {0.f, 0.f, 0.f, 0.f};
        float c1[4] = {0.f, 0.f, 0.f, 0.f};

        #pragma unroll
        for (int ky = 0; ky < 3; ky++) {
            const uint32_t rbw = (uint32_t)((r + ky) * ROW_W + (posbase + lm) * 16 + 2 * lk);
            const uint32_t* bp = Bf + ky * 6 * 128 + lane * 2;
            #pragma unroll
            for (int ks = 0; ks < 6; ks++) {
                uint32_t sw = swzw(rbw + (uint32_t)((ks >> 1) * 16 + (ks & 1) * 8));
                uint2 lo = *(const uint2*)(Asm + sw);         // a0, a2
                uint2 hi = *(const uint2*)(Asm + sw + 128);   // a1, a3
                uint2 b0 = *(const uint2*)(bp + ks * 128);
                uint2 b1 = *(const uint2*)(bp + ks * 128 + 64);
                mma_tf32(c0, lo.x, hi.x, lo.y, hi.y, b0.x, b0.y);
                mma_tf32(c1, lo.x, hi.x, lo.y, hi.y, b1.x, b1.y);
            }
        }

        if (yo < OUT_W) {
            int xoA = X0 + posbase + lm;
            int xoB = xoA + 8;
            float* yn = y + ((size_t)n * 16) * (OUT_W * OUT_W) + (size_t)yo * OUT_W;
            #pragma unroll
            for (int h = 0; h < 2; h++) {
                const float* cc = h ? c1 : c0;
                int coA = h * 8 + lk * 2;
                float bA = bsm[coA]     - 0.7f;
                float bB = bsm[coA + 1] - 0.7f;
                if (xoA < OUT_W) {
                    yn[(size_t)coA       * (OUT_W * OUT_W) + xoA] = mish_f(cc[0] + bA);
                    yn[(size_t)(coA + 1) * (OUT_W * OUT_W) + xoA] = mish_f(cc[1] + bB);
                }
                if (xoB < OUT_W) {
                    yn[(size_t)coA       * (OUT_W * OUT_W) + xoB] = mish_f(cc[2] + bA);
                    yn[(size_t)(coA + 1) * (OUT_W * OUT_W) + xoB] = mish_f(cc[3] + bB);
                }
            }
        }
    }
}

extern "C" void kernel_launch(void* const* d_in, const int* in_sizes, int n_in,
                              void* d_out, int out_size)
{
    const float* x  = (const float*)d_in[0];
    const float* w  = (const float*)d_in[1];
    const float* b  = (const float*)d_in[2];
    float* y = (float*)d_out;

    cudaFuncSetAttribute(conv_tc_kernel,
                         cudaFuncAttributeMaxDynamicSharedMemorySize, SMEM_BYTES);

    int N = in_sizes[0] / (16 * IN_HW);                 // 32
    dim3 grid(2, (OUT_W + R_OUT - 1) / R_OUT, N);       // 2 x 64 x 32
    conv_tc_kernel<<<grid, 256, SMEM_BYTES>>>(x, w, b, y);
}

// round 7
// speedup vs baseline: 1.5896x; 1.5896x over previous
#include <cuda_runtime.h>
#include <stdint.h>

#define IN_W 256
#define IN_HW 65536
#define OUT_W 254

#define R_OUT 8            // output rows per CTA
#define ROWS_IN 10         // R_OUT + 2
#define POS 130            // 128 + 2 halo input positions
#define ROW_W 2080         // POS * 16 words per input row
#define A_WORDS (ROWS_IN * ROW_W)        // 20800
#define BF_WORDS 2304                    // 3 ky * 6 ks * 2 h * 32 lanes * 2 regs
#define SMEM_BYTES ((A_WORDS + BF_WORDS + 16) * 4)   // 92,544 B -> 2 CTAs/SM

// word-index swizzle: XOR bits[5:7) into bits[2:4) (R5-proven conflict-free
// for LDS.32 fragment loads and the STS.128 transpose stores)
__device__ __forceinline__ uint32_t swzw(uint32_t w) {
    return w ^ (((w >> 5) & 3u) << 2);
}
__device__ __forceinline__ uint32_t tf32r(float f) {
    uint32_t r; asm("cvt.rna.tf32.f32 %0, %1;" : "=r"(r) : "f"(f)); return r;
}
__device__ __forceinline__ void mma_tf32(float c[4], uint32_t a0, uint32_t a1,
                                         uint32_t a2, uint32_t a3,
                                         uint32_t b0, uint32_t b1) {
    asm("mma.sync.aligned.m16n8k8.row.col.f32.tf32.tf32.f32 "
        "{%0,%1,%2,%3}, {%4,%5,%6,%7}, {%8,%9}, {%0,%1,%2,%3};"
        : "+f"(c[0]), "+f"(c[1]), "+f"(c[2]), "+f"(c[3])
        : "r"(a0), "r"(a1), "r"(a2), "r"(a3), "r"(b0), "r"(b1));
}
__device__ __forceinline__ float mish_f(float v) {
    if (v > 30.0f) return v;
    float e  = __expf(v);
    float t  = 1.0f + e;
    float t2 = t * t;
    return v * __fdividef(t2 - 1.0f, t2 + 1.0f);
}

__global__ __launch_bounds__(256, 2)
void conv_tc_kernel(const float* __restrict__ x,
                    const float* __restrict__ w,
                    const float* __restrict__ bias,
                    float* __restrict__ y)
{
    extern __shared__ uint32_t sm[];
    uint32_t* Asm = sm;                     // [row][pos][ci16], swizzled tf32
    uint32_t* Bf  = sm + A_WORDS;           // lane-ordered B fragments
    float*    bsm = (float*)(sm + A_WORDS + BF_WORDS);

    const int tid  = threadIdx.x;
    const int wid  = tid >> 5;
    const int lane = tid & 31;
    const int lm   = lane >> 2;
    const int lk   = lane & 3;
    const int X0   = blockIdx.x * 128;
    const int Y0   = blockIdx.y * R_OUT;
    const int n    = blockIdx.z;

    if (tid < 16) bsm[tid] = bias[tid];

    // ---- B fragments: Bf[(ky*6+ks)*128 + h*64 + lane*2 + reg]
    for (int i = tid; i < BF_WORDS; i += 256) {
        int reg = i & 1;
        int ln  = (i >> 1) & 31;
        int h   = (i >> 6) & 1;
        int t   = i >> 7;              // ky*6+ks
        int ks  = t % 6, ky = t / 6;
        int k   = ks * 8 + (ln & 3) + reg * 4;
        int co  = h * 8 + (ln >> 2);
        int kx  = k >> 4, ci = k & 15;
        Bf[i] = tf32r(w[(co * 16 + ci) * 9 + ky * 3 + kx]);
    }

    // ---- input transpose: NCHW -> smem [row][pos][ci], tf32, swizzled (R5 layout)
    const float* xn = x + (size_t)n * 16 * IN_HW;
    for (int i = tid; i < ROWS_IN * POS; i += 256) {
        int pos = i % POS;
        int row = i / POS;
        int gy = Y0 + row; if (gy > 255) gy = 255;   // clamped rows feed guarded outputs only
        int gx = X0 + pos; if (gx > 255) gx = 255;
        const float* src = xn + gy * IN_W + gx;
        uint32_t wb = row * ROW_W + pos * 16;
        #pragma unroll
        for (int c4 = 0; c4 < 4; c4++) {
            uint4 q;
            q.x = tf32r(src[(size_t)(c4 * 4 + 0) * IN_HW]);
            q.y = tf32r(src[(size_t)(c4 * 4 + 1) * IN_HW]);
            q.z = tf32r(src[(size_t)(c4 * 4 + 2) * IN_HW]);
            q.w = tf32r(src[(size_t)(c4 * 4 + 3) * IN_HW]);
            *(uint4*)(Asm + swzw(wb + c4 * 4)) = q;
        }
    }
    __syncthreads();

    // ---- mainloop: warp wid -> output row Y0+wid; 4 iters x 2 tiles (32 x's)
    const int r  = wid;
    const int yo = Y0 + r;

    #pragma unroll 1
    for (int t = 0; t < 4; t++) {
        const int posbase = t * 32;
        float c[2][2][4];           // [tile][n-half][regs] : 4 independent chains
        #pragma unroll
        for (int u = 0; u < 2; u++)
            #pragma unroll
            for (int h = 0; h < 2; h++)
                #pragma unroll
                for (int e = 0; e < 4; e++) c[u][h][e] = 0.f;

        #pragma unroll
        for (int ky = 0; ky < 3; ky++) {
            const uint32_t rb = (uint32_t)((r + ky) * ROW_W + (posbase + lm) * 16 + lk);
            const uint32_t* bp = Bf + ky * 6 * 128 + lane * 2;
            #pragma unroll
            for (int ks = 0; ks < 6; ks++) {
                uint32_t sw  = swzw(rb + ks * 8);   // tile1 = +256 (swizzle-invariant)
                uint32_t sw4 = sw ^ 4u;
                uint2 b0 = *(const uint2*)(bp + ks * 128);
                uint2 b1 = *(const uint2*)(bp + ks * 128 + 64);
                uint32_t a0 = Asm[sw];
                uint32_t a1 = Asm[sw + 128];
                uint32_t a2 = Asm[sw4];
                uint32_t a3 = Asm[sw4 + 128];
                mma_tf32(c[0][0], a0, a1, a2, a3, b0.x, b0.y);
                mma_tf32(c[0][1], a0, a1, a2, a3, b1.x, b1.y);
                uint32_t a4 = Asm[sw + 256];
                uint32_t a5 = Asm[sw + 384];
                uint32_t a6 = Asm[sw4 + 256];
                uint32_t a7 = Asm[sw4 + 384];
                mma_tf32(c[1][0], a4, a5, a6, a7, b0.x, b0.y);
                mma_tf32(c[1][1], a4, a5, a6, a7, b1.x, b1.y);
            }
        }

        if (yo < OUT_W) {
            float* yn = y + ((size_t)n * 16) * (OUT_W * OUT_W) + (size_t)yo * OUT_W;
            #pragma unroll
            for (int u = 0; u < 2; u++) {
                int xoA = X0 + posbase + u * 16 + lm;
                int xoB = xoA + 8;
                #pragma unroll
                for (int h = 0; h < 2; h++) {
                    const float* cc = c[u][h];
                    int coA = h * 8 + lk * 2;
                    float bA = bsm[coA]     - 0.7f;
                    float bB = bsm[coA + 1] - 0.7f;
                    if (xoA < OUT_W) {
                        yn[(size_t)coA       * (OUT_W * OUT_W) + xoA] = mish_f(cc[0] + bA);
                        yn[(size_t)(coA + 1) * (OUT_W * OUT_W) + xoA] = mish_f(cc[1] + bB);
                    }
                    if (xoB < OUT_W) {
                        yn[(size_t)coA       * (OUT_W * OUT_W) + xoB] = mish_f(cc[2] + bA);
                        yn[(size_t)(coA + 1) * (OUT_W * OUT_W) + xoB] = mish_f(cc[3] + bB);
                    }
                }
            }
        }
    }
}

extern "C" void kernel_launch(void* const* d_in, const int* in_sizes, int n_in,
                              void* d_out, int out_size)
{
    const float* x  = (const float*)d_in[0];
    const float* w  = (const float*)d_in[1];
    const float* b  = (const float*)d_in[2];
    float* y = (float*)d_out;

    cudaFuncSetAttribute(conv_tc_kernel,
                         cudaFuncAttributeMaxDynamicSharedMemorySize, SMEM_BYTES);

    int N = in_sizes[0] / (16 * IN_HW);                 // 32
    dim3 grid(2, (OUT_W + R_OUT - 1) / R_OUT, N);       // 2 x 32 x 32
    conv_tc_kernel<<<grid, 256, SMEM_BYTES>>>(x, w, b, y);
}